// round 15
// baseline (speedup 1.0000x reference)
#include <cuda_runtime.h>
#include <cuda_bf16.h>
#include <math.h>

// Problem constants
#define B_  64
#define T_  512
#define I_  512
#define H_  1024
#define G4  4096           // 4*H
#define BH  (B_*H_)        // 65536
#define NCTA 128
#define BK  32
#define NSTAGE (H_/BK)     // 32
#define NTHR 512

typedef unsigned long long u64;
typedef unsigned int u32;

// ---------------------------------------------------------------------------
// Device scratch
// ---------------------------------------------------------------------------
__device__ float g_xp[(size_t)2 * T_ * B_ * G4];   // xp[dir][t][b][g]  (1 GiB)
__device__ float g_wT[2][H_][G4];                  // w_hh transposed [dir][k][n] (32 MB)
__device__ float g_hT[2][2][H_][B_];               // h: [phase][dir][j][b]
__device__ unsigned g_bar_count;
__device__ volatile unsigned g_bar_sense;

// ---------------------------------------------------------------------------
// PTX helpers
// ---------------------------------------------------------------------------
__device__ __forceinline__ void fma2(u64& c, u64 a, u64 b) {
    asm volatile("fma.rn.f32x2 %0, %1, %2, %0;" : "+l"(c) : "l"(a), "l"(b));
}
__device__ __forceinline__ u64 rep2(float x) {
    u64 r;
    asm volatile("mov.b64 %0, {%1, %1};" : "=l"(r) : "f"(x));
    return r;
}
__device__ __forceinline__ void cp_async16(u32 smem_addr, const void* gptr) {
    asm volatile("cp.async.cg.shared.global [%0], [%1], 16;" :: "r"(smem_addr), "l"(gptr));
}
__device__ __forceinline__ void cp_commit() { asm volatile("cp.async.commit_group;"); }
__device__ __forceinline__ void cp_wait1()  { asm volatile("cp.async.wait_group 1;"); }
__device__ __forceinline__ void cp_wait0()  { asm volatile("cp.async.wait_group 0;"); }
__device__ __forceinline__ float lo32(u64 v) { return __uint_as_float((u32)(v & 0xffffffffull)); }
__device__ __forceinline__ float hi32(u64 v) { return __uint_as_float((u32)(v >> 32)); }

// ---------------------------------------------------------------------------
// Init (every replay): zero h(phase 0) and barrier state
// ---------------------------------------------------------------------------
__global__ void init_state_kernel() {
    int i = blockIdx.x * blockDim.x + threadIdx.x;
    if (i < 2 * BH) ((float*)g_hT)[i] = 0.0f;
    if (i == 0) { g_bar_count = 0; g_bar_sense = 0; }
}

// ---------------------------------------------------------------------------
// Transpose w_hh [4096,1024] -> g_wT [dir][1024][4096]
// ---------------------------------------------------------------------------
__global__ void __launch_bounds__(256) transpose_w_kernel(
    const float* __restrict__ wfw, const float* __restrict__ wbw)
{
    __shared__ float tile[32][33];
    const int dir = blockIdx.z;
    const float* w = dir ? wbw : wfw;
    const int n0 = blockIdx.x * 32;
    const int k0 = blockIdx.y * 32;
    const int tx = threadIdx.x & 31, ty = threadIdx.x >> 5;
#pragma unroll
    for (int r = 0; r < 32; r += 8)
        tile[ty + r][tx] = w[(size_t)(n0 + ty + r) * H_ + k0 + tx];
    __syncthreads();
#pragma unroll
    for (int r = 0; r < 32; r += 8)
        g_wT[dir][k0 + ty + r][n0 + tx] = tile[tx][ty + r];
}

// ---------------------------------------------------------------------------
// Input projection (R2 version — known good)
// ---------------------------------------------------------------------------
__global__ void __launch_bounds__(128) input_proj_kernel(
    const float* __restrict__ x,
    const float* __restrict__ w_fw, const float* __restrict__ w_bw,
    const float* __restrict__ bi_fw, const float* __restrict__ bh_fw,
    const float* __restrict__ bi_bw, const float* __restrict__ bh_bw)
{
    const int gt  = blockIdx.x;
    const int t   = blockIdx.y;
    const int dir = blockIdx.z;

    const float* w     = dir ? w_bw : w_fw;
    const float* bi    = dir ? bi_bw : bi_fw;
    const float* bh    = dir ? bh_bw : bh_fw;
    const int    src_t = dir ? (T_ - 1 - t) : t;

    __shared__ float sA[16][68];
    __shared__ float sB[16][68];

    const int tid = threadIdx.x;
    const int tr  = tid >> 4;
    const int tc  = tid & 15;

    u64 acc[4][4];
#pragma unroll
    for (int p = 0; p < 4; p++)
#pragma unroll
        for (int j = 0; j < 4; j++) acc[p][j] = 0ull;

    const float* Abase = x + (size_t)src_t * I_;
    const float* Bbase = w + (size_t)(gt * 64) * I_;

    for (int k0 = 0; k0 < I_; k0 += 16) {
#pragma unroll 4
        for (int idx = tid; idx < 1024; idx += 128) {
            int kk = idx & 15, m = idx >> 4;
            sA[kk][m] = Abase[(size_t)m * (T_ * I_) + k0 + kk];
        }
#pragma unroll 4
        for (int idx = tid; idx < 1024; idx += 128) {
            int kk = idx & 15, n = idx >> 4;
            sB[kk][n] = Bbase[(size_t)n * I_ + k0 + kk];
        }
        __syncthreads();
#pragma unroll
        for (int kk = 0; kk < 16; kk++) {
            const float* ap = &sA[kk][tr * 8];
            u64 a0 = *(const u64*)(ap + 0);
            u64 a1 = *(const u64*)(ap + 2);
            u64 a2 = *(const u64*)(ap + 4);
            u64 a3 = *(const u64*)(ap + 6);
            float4 b4 = *(const float4*)&sB[kk][tc * 4];
            u64 b0 = rep2(b4.x), b1 = rep2(b4.y), b2 = rep2(b4.z), b3 = rep2(b4.w);
            fma2(acc[0][0], a0, b0); fma2(acc[0][1], a0, b1); fma2(acc[0][2], a0, b2); fma2(acc[0][3], a0, b3);
            fma2(acc[1][0], a1, b0); fma2(acc[1][1], a1, b1); fma2(acc[1][2], a1, b2); fma2(acc[1][3], a1, b3);
            fma2(acc[2][0], a2, b0); fma2(acc[2][1], a2, b1); fma2(acc[2][2], a2, b2); fma2(acc[2][3], a2, b3);
            fma2(acc[3][0], a3, b0); fma2(acc[3][1], a3, b1); fma2(acc[3][2], a3, b2); fma2(acc[3][3], a3, b3);
        }
        __syncthreads();
    }

    const int gbase = gt * 64 + tc * 4;
    float bias[4];
#pragma unroll
    for (int j = 0; j < 4; j++) bias[j] = bi[gbase + j] + bh[gbase + j];

    float* outp = g_xp + (((size_t)dir * T_ + t) * B_) * G4;
#pragma unroll
    for (int i = 0; i < 8; i++) {
        int m = tr * 8 + i;
        int p = i >> 1;
        float v0 = (i & 1) ? hi32(acc[p][0]) : lo32(acc[p][0]);
        float v1 = (i & 1) ? hi32(acc[p][1]) : lo32(acc[p][1]);
        float v2 = (i & 1) ? hi32(acc[p][2]) : lo32(acc[p][2]);
        float v3 = (i & 1) ? hi32(acc[p][3]) : lo32(acc[p][3]);
        float4 v = make_float4(v0 + bias[0], v1 + bias[1], v2 + bias[2], v3 + bias[3]);
        *(float4*)(outp + (size_t)m * G4 + gbase) = v;
    }
}

// ---------------------------------------------------------------------------
// Persistent LSTM recurrence.
// grid=128 (dir,jt per CTA), block=512 (16 warps = 4x4 grid of 16x16 subtiles).
// Warp (wr,wc): rows 16wr..+15, cols 16wc..+15. Lane: 4 rows x 2 cols.
// Per warp-kk: A = 1 LDS.128 wavefront, B = 1 LDS.64 wavefront (2 wf total,
// half of R13's 4) -> smem crossbar balanced 1:1 with FFMA2 pipe.
// Both operands bulk cp.async staged (triple-buffered, 1 sync/stage).
// c state + xp prefetch in registers. Grid barrier between steps.
// smem: sA[3][32*64] | sB[3][32*64] (48 KB); sG[64*66] aliases sA.
// RACE FIX (R12): __syncthreads() between last GEMM stage and sG alias writes.
// ---------------------------------------------------------------------------
#define SA_FLOATS (3 * BK * 64)    // 6144
#define SB_FLOATS (3 * BK * 64)    // 6144
#define SG_STRIDE 66               // even -> 8B-aligned float2 rows

__global__ void __launch_bounds__(NTHR, 1) lstm_persistent_kernel(float* __restrict__ out)
{
    __shared__ __align__(16) float smem[SA_FLOATS + SB_FLOATS];   // 48 KB
    float* sA = smem;
    float* sB = smem + SA_FLOATS;
    float* sG = smem;                                // alias sA (64*66=4224<=6144)

    const int bx  = blockIdx.x;
    const int dir = bx & 1;
    const int jt  = bx >> 1;                 // 0..63

    const int tid  = threadIdx.x;
    const int w    = tid >> 5;               // warp 0..15
    const int l    = tid & 31;               // lane
    const int wr   = w & 3;                  // warp-row: rows 16wr..+15
    const int wc   = w >> 2;                 // warp-col: cols 16wc..+15
    const int rg   = l >> 3;                 // lane row-group: rows 16wr+4rg..+3
    const int cp   = l & 7;                  // lane col-pair: cols 16wc+2cp, +1
    const int m0   = 16 * wr + 4 * rg;       // first row of lane's 4
    const int n0   = 16 * wc + 2 * cp;       // first col of lane's 2

    const float* wT = &g_wT[dir][0][0];
    const u32 sA_u = (u32)__cvta_generic_to_shared(sA);
    const u32 sB_u = (u32)__cvta_generic_to_shared(sB);

    // B cp.async source for this thread's single chunk:
    // tid in [0,512): kk=tid>>4, piece=tid&15, q=piece>>2, sub=piece&3
    const int b_kk = tid >> 4;
    const int b_pc = tid & 15;
    const int pc_q = b_pc >> 2, pc_s = b_pc & 3;
    const size_t bcol_off = (size_t)(pc_q * H_ + jt * 16 + pc_s * 4);
    const u32 b_sm_off = (u32)((b_kk * 256) + (pc_q * 16 + pc_s * 4) * 4);

    // activation cells: p4 = tid + r*512, r=0..1 (b, j fixed across t)
    int cell_b[2], cell_j[2];
#pragma unroll
    for (int r = 0; r < 2; r++) { cell_b[r] = (tid + r * NTHR) >> 4; cell_j[r] = (tid + r * NTHR) & 15; }

    float creg[2] = {0.0f, 0.0f};

    for (int t = 0; t < T_; t++) {
        const int phase = t & 1;
        const float* hT  = &g_hT[phase][dir][0][0];
        float*       hTn = &g_hT[phase ^ 1][dir][0][0];
        const float* xp  = g_xp + ((size_t)dir * T_ + t) * B_ * G4;

        // prefetch this thread's 8 xp gate values (completes during GEMM)
        float xg[2][4];
#pragma unroll
        for (int r = 0; r < 2; r++)
#pragma unroll
            for (int g = 0; g < 4; g++)
                xg[r][g] = __ldg(xp + (size_t)cell_b[r] * G4 + g * H_ + jt * 16 + cell_j[r]);

        u64 acc[2][2];
        acc[0][0] = acc[0][1] = acc[1][0] = acc[1][1] = 0ull;

#define ISSUE(s) do {                                                             \
            const int _s = (s);                                                   \
            const int _buf = _s % 3;                                              \
            const u32 _ad = sA_u + (u32)(_buf * BK * 64 * 4);                     \
            const u32 _bd = sB_u + (u32)(_buf * BK * 64 * 4);                     \
            cp_async16(_ad + (u32)tid * 16, hT + (size_t)_s * 2048 + tid * 4);    \
            cp_async16(_bd + b_sm_off,                                            \
                       wT + (size_t)(_s * BK + b_kk) * G4 + bcol_off);            \
            cp_commit();                                                          \
        } while (0)

        ISSUE(0);
        ISSUE(1);

        for (int s = 0; s < NSTAGE; s++) {
            if (s + 1 < NSTAGE) cp_wait1(); else cp_wait0();
            __syncthreads();
            if (s + 2 < NSTAGE) ISSUE(s + 2);

            const float* A  = sA + (s % 3) * (BK * 64) + m0;   // 16B-aligned
            const float* Bm = sB + (s % 3) * (BK * 64) + n0;   //  8B-aligned
#pragma unroll
            for (int kk = 0; kk < BK; kk++) {
                // A: one LDS.128 -> rows m0..m0+3 as two aligned reg pairs
                double2 ad = *(const double2*)(A + kk * 64);
                u64 a0 = __double_as_longlong(ad.x);   // rows m0, m0+1
                u64 a1 = __double_as_longlong(ad.y);   // rows m0+2, m0+3
                // B: one LDS.64 -> cols n0, n0+1
                u64 bv = __double_as_longlong(*(const double*)(Bm + kk * 64));
                u64 b0 = rep2(lo32(bv));
                u64 b1 = rep2(hi32(bv));
                fma2(acc[0][0], a0, b0); fma2(acc[0][1], a0, b1);
                fma2(acc[1][0], a1, b0); fma2(acc[1][1], a1, b1);
            }
        }
#undef ISSUE

        // RACE FIX: all warps must finish READING the last stage's A/B buffers
        // before sG (which aliases them) is written.
        __syncthreads();

        // ---- stage raw GEMM sums into sG[64][66] (aliases sA; drained) ----
        // acc[p][j]: lo = cell(m0+2p, n0+j), hi = cell(m0+2p+1, n0+j)
#pragma unroll
        for (int p = 0; p < 2; p++) {
            int m = m0 + 2 * p;
            float2 v_lo = make_float2(lo32(acc[p][0]), lo32(acc[p][1]));
            float2 v_hi = make_float2(hi32(acc[p][0]), hi32(acc[p][1]));
            *(float2*)(sG + (m + 0) * SG_STRIDE + n0) = v_lo;
            *(float2*)(sG + (m + 1) * SG_STRIDE + n0) = v_hi;
        }
        __syncthreads();

        // ---- activation + state update: 2 cells/thread ----
#pragma unroll
        for (int r = 0; r < 2; r++) {
            int b = cell_b[r], j = cell_j[r];
            int jc = jt * 16 + j;

            float ig = sG[b * SG_STRIDE +      j] + xg[r][0];
            float fg = sG[b * SG_STRIDE + 16 + j] + xg[r][1];
            float gg = sG[b * SG_STRIDE + 32 + j] + xg[r][2];
            float og = sG[b * SG_STRIDE + 48 + j] + xg[r][3];

            float si = 1.0f / (1.0f + __expf(-ig));
            float sf = 1.0f / (1.0f + __expf(-fg));
            float so = 1.0f / (1.0f + __expf(-og));
            float cn = sf * creg[r] + si * tanhf(gg);
            float hn = so * tanhf(cn);
            creg[r] = cn;

            hTn[jc * B_ + b] = hn;
            out[((size_t)b * T_ + t) * (2 * H_) + dir * H_ + jc] = hn;

            if (t == T_ - 1) {
                const size_t base = (size_t)B_ * T_ * 2 * H_;
                out[base + (dir ? 2 : 0) * (size_t)BH + b * H_ + jc] = hn;
                out[base + (dir ? 3 : 1) * (size_t)BH + b * H_ + jc] = cn;
            }
        }

        // ---- grid barrier ----
        __threadfence();
        __syncthreads();
        if (tid == 0) {
            unsigned ticket = atomicAdd(&g_bar_count, 1u);
            if (ticket == NCTA - 1) {
                g_bar_count = 0;
                __threadfence();
                g_bar_sense = (unsigned)(t + 1);
            } else {
                while (g_bar_sense < (unsigned)(t + 1)) { __nanosleep(32); }
            }
        }
        __syncthreads();
    }
}

// ---------------------------------------------------------------------------
// Launch
// ---------------------------------------------------------------------------
extern "C" void kernel_launch(void* const* d_in, const int* in_sizes, int n_in,
                              void* d_out, int out_size) {
    (void)in_sizes; (void)n_in; (void)out_size;
    const float* x       = (const float*)d_in[0];
    const float* w_ih_fw = (const float*)d_in[1];
    const float* w_hh_fw = (const float*)d_in[2];
    const float* b_ih_fw = (const float*)d_in[3];
    const float* b_hh_fw = (const float*)d_in[4];
    const float* w_ih_bw = (const float*)d_in[5];
    const float* w_hh_bw = (const float*)d_in[6];
    const float* b_ih_bw = (const float*)d_in[7];
    const float* b_hh_bw = (const float*)d_in[8];
    float* out = (float*)d_out;

    init_state_kernel<<<(2 * BH + 255) / 256, 256>>>();

    dim3 gtw(G4 / 32, H_ / 32, 2);
    transpose_w_kernel<<<gtw, 256>>>(w_hh_fw, w_hh_bw);

    dim3 gproj(64, T_, 2);
    input_proj_kernel<<<gproj, 128>>>(x, w_ih_fw, w_ih_bw,
                                      b_ih_fw, b_hh_fw, b_ih_bw, b_hh_bw);

    lstm_persistent_kernel<<<NCTA, NTHR>>>(out);
}

// round 16
// speedup vs baseline: 1.3184x; 1.3184x over previous
#include <cuda_runtime.h>
#include <cuda_bf16.h>
#include <math.h>

// Problem constants
#define B_  64
#define T_  512
#define I_  512
#define H_  1024
#define G4  4096           // 4*H
#define BH  (B_*H_)        // 65536
#define NCTA 128
#define BK  32
#define NSTAGE (H_/BK)     // 32
#define NTHR 512

typedef unsigned long long u64;
typedef unsigned int u32;

// ---------------------------------------------------------------------------
// Device scratch
// ---------------------------------------------------------------------------
__device__ float g_xp[(size_t)2 * T_ * B_ * G4];   // xp[dir][t][b][g]  (1 GiB)
__device__ float g_wT[2][H_][G4];                  // w_hh transposed [dir][k][n] (32 MB)
__device__ float g_hT[2][2][H_][B_];               // h: [phase][dir][j][b]
__device__ unsigned g_bar_count;
__device__ volatile unsigned g_bar_sense;

// ---------------------------------------------------------------------------
// PTX helpers
// ---------------------------------------------------------------------------
__device__ __forceinline__ void fma2(u64& c, u64 a, u64 b) {
    asm volatile("fma.rn.f32x2 %0, %1, %2, %0;" : "+l"(c) : "l"(a), "l"(b));
}
__device__ __forceinline__ u64 rep2(float x) {
    u64 r;
    asm volatile("mov.b64 %0, {%1, %1};" : "=l"(r) : "f"(x));
    return r;
}
__device__ __forceinline__ void cp_async16(u32 smem_addr, const void* gptr) {
    asm volatile("cp.async.cg.shared.global [%0], [%1], 16;" :: "r"(smem_addr), "l"(gptr));
}
__device__ __forceinline__ void cp_commit() { asm volatile("cp.async.commit_group;"); }
__device__ __forceinline__ void cp_wait1()  { asm volatile("cp.async.wait_group 1;"); }
__device__ __forceinline__ void cp_wait0()  { asm volatile("cp.async.wait_group 0;"); }
__device__ __forceinline__ float lo32(u64 v) { return __uint_as_float((u32)(v & 0xffffffffull)); }
__device__ __forceinline__ float hi32(u64 v) { return __uint_as_float((u32)(v >> 32)); }

// ---------------------------------------------------------------------------
// Init (every replay): zero h(phase 0) and barrier state
// ---------------------------------------------------------------------------
__global__ void init_state_kernel() {
    int i = blockIdx.x * blockDim.x + threadIdx.x;
    if (i < 2 * BH) ((float*)g_hT)[i] = 0.0f;
    if (i == 0) { g_bar_count = 0; g_bar_sense = 0; }
}

// ---------------------------------------------------------------------------
// Transpose w_hh [4096,1024] -> g_wT [dir][1024][4096]
// ---------------------------------------------------------------------------
__global__ void __launch_bounds__(256) transpose_w_kernel(
    const float* __restrict__ wfw, const float* __restrict__ wbw)
{
    __shared__ float tile[32][33];
    const int dir = blockIdx.z;
    const float* w = dir ? wbw : wfw;
    const int n0 = blockIdx.x * 32;
    const int k0 = blockIdx.y * 32;
    const int tx = threadIdx.x & 31, ty = threadIdx.x >> 5;
#pragma unroll
    for (int r = 0; r < 32; r += 8)
        tile[ty + r][tx] = w[(size_t)(n0 + ty + r) * H_ + k0 + tx];
    __syncthreads();
#pragma unroll
    for (int r = 0; r < 32; r += 8)
        g_wT[dir][k0 + ty + r][n0 + tx] = tile[tx][ty + r];
}

// ---------------------------------------------------------------------------
// Input projection (R2 version — known good)
// ---------------------------------------------------------------------------
__global__ void __launch_bounds__(128) input_proj_kernel(
    const float* __restrict__ x,
    const float* __restrict__ w_fw, const float* __restrict__ w_bw,
    const float* __restrict__ bi_fw, const float* __restrict__ bh_fw,
    const float* __restrict__ bi_bw, const float* __restrict__ bh_bw)
{
    const int gt  = blockIdx.x;
    const int t   = blockIdx.y;
    const int dir = blockIdx.z;

    const float* w     = dir ? w_bw : w_fw;
    const float* bi    = dir ? bi_bw : bi_fw;
    const float* bh    = dir ? bh_bw : bh_fw;
    const int    src_t = dir ? (T_ - 1 - t) : t;

    __shared__ float sA[16][68];
    __shared__ float sB[16][68];

    const int tid = threadIdx.x;
    const int tr  = tid >> 4;
    const int tc  = tid & 15;

    u64 acc[4][4];
#pragma unroll
    for (int p = 0; p < 4; p++)
#pragma unroll
        for (int j = 0; j < 4; j++) acc[p][j] = 0ull;

    const float* Abase = x + (size_t)src_t * I_;
    const float* Bbase = w + (size_t)(gt * 64) * I_;

    for (int k0 = 0; k0 < I_; k0 += 16) {
#pragma unroll 4
        for (int idx = tid; idx < 1024; idx += 128) {
            int kk = idx & 15, m = idx >> 4;
            sA[kk][m] = Abase[(size_t)m * (T_ * I_) + k0 + kk];
        }
#pragma unroll 4
        for (int idx = tid; idx < 1024; idx += 128) {
            int kk = idx & 15, n = idx >> 4;
            sB[kk][n] = Bbase[(size_t)n * I_ + k0 + kk];
        }
        __syncthreads();
#pragma unroll
        for (int kk = 0; kk < 16; kk++) {
            const float* ap = &sA[kk][tr * 8];
            u64 a0 = *(const u64*)(ap + 0);
            u64 a1 = *(const u64*)(ap + 2);
            u64 a2 = *(const u64*)(ap + 4);
            u64 a3 = *(const u64*)(ap + 6);
            float4 b4 = *(const float4*)&sB[kk][tc * 4];
            u64 b0 = rep2(b4.x), b1 = rep2(b4.y), b2 = rep2(b4.z), b3 = rep2(b4.w);
            fma2(acc[0][0], a0, b0); fma2(acc[0][1], a0, b1); fma2(acc[0][2], a0, b2); fma2(acc[0][3], a0, b3);
            fma2(acc[1][0], a1, b0); fma2(acc[1][1], a1, b1); fma2(acc[1][2], a1, b2); fma2(acc[1][3], a1, b3);
            fma2(acc[2][0], a2, b0); fma2(acc[2][1], a2, b1); fma2(acc[2][2], a2, b2); fma2(acc[2][3], a2, b3);
            fma2(acc[3][0], a3, b0); fma2(acc[3][1], a3, b1); fma2(acc[3][2], a3, b2); fma2(acc[3][3], a3, b3);
        }
        __syncthreads();
    }

    const int gbase = gt * 64 + tc * 4;
    float bias[4];
#pragma unroll
    for (int j = 0; j < 4; j++) bias[j] = bi[gbase + j] + bh[gbase + j];

    float* outp = g_xp + (((size_t)dir * T_ + t) * B_) * G4;
#pragma unroll
    for (int i = 0; i < 8; i++) {
        int m = tr * 8 + i;
        int p = i >> 1;
        float v0 = (i & 1) ? hi32(acc[p][0]) : lo32(acc[p][0]);
        float v1 = (i & 1) ? hi32(acc[p][1]) : lo32(acc[p][1]);
        float v2 = (i & 1) ? hi32(acc[p][2]) : lo32(acc[p][2]);
        float v3 = (i & 1) ? hi32(acc[p][3]) : lo32(acc[p][3]);
        float4 v = make_float4(v0 + bias[0], v1 + bias[1], v2 + bias[2], v3 + bias[3]);
        *(float4*)(outp + (size_t)m * G4 + gbase) = v;
    }
}

// ---------------------------------------------------------------------------
// Persistent LSTM recurrence, split-K x4.
// grid=128 (dir,jt per CTA), block=512 (16 warps).
// Group g = warps 4g..4g+3 (128 thr): kk in [8g, 8g+8) of EVERY stage, with
// an 8-row x 4-col microtile over the full 64x64 tile -> 1.5 B/MAC (vs 3.0),
// crossbar ceiling 66% fma (vs 33% measured at the old shape).
// Staging/ring/syncs identical to the passing R15 kernel.
// Partials: 4 sG regions (stride 68, 16B rows); activation sums 4.
// smem (dynamic 68KB): ring sA[3][2048]|sB[3][2048] = 48KB; sG4[4][64][68]
// aliases from 0 (written only after the post-loop race-fix sync).
// ---------------------------------------------------------------------------
#define SA_FLOATS (3 * BK * 64)    // 6144
#define SB_FLOATS (3 * BK * 64)    // 6144
#define SG_STRIDE 68               // 68*4=272 B rows: 16B-aligned
#define SG_REGION (64 * SG_STRIDE) // 4352 floats per group region
#define SMEM_BYTES (4 * SG_REGION * 4)   // 69632 > 49152 ring: dyn size

__global__ void __launch_bounds__(NTHR, 1) lstm_persistent_kernel(float* __restrict__ out)
{
    extern __shared__ __align__(16) float smem[];
    float* sA = smem;
    float* sB = smem + SA_FLOATS;
    float* sG = smem;                        // 4 regions of 4352 floats

    const int bx  = blockIdx.x;
    const int dir = bx & 1;
    const int jt  = bx >> 1;                 // 0..63

    const int tid = threadIdx.x;
    const int g   = tid >> 7;                // K-group 0..3
    const int loc = tid & 127;
    const int tr  = loc >> 4;                // 0..7 -> rows tr*8..+7
    const int tc  = loc & 15;                // 0..15 -> cols tc*4..+3

    const float* wT = &g_wT[dir][0][0];
    const u32 sA_u = (u32)__cvta_generic_to_shared(sA);
    const u32 sB_u = (u32)__cvta_generic_to_shared(sB);

    // staging assignment (identical to R15)
    const int b_kk = tid >> 4;
    const int b_pc = tid & 15;
    const int pc_q = b_pc >> 2, pc_s = b_pc & 3;
    const size_t bcol_off = (size_t)(pc_q * H_ + jt * 16 + pc_s * 4);
    const u32 b_sm_off = (u32)((b_kk * 256) + (pc_q * 16 + pc_s * 4) * 4);

    // activation cells: p4 = tid + r*512
    int cell_b[2], cell_j[2];
#pragma unroll
    for (int r = 0; r < 2; r++) { cell_b[r] = (tid + r * NTHR) >> 4; cell_j[r] = (tid + r * NTHR) & 15; }

    float creg[2] = {0.0f, 0.0f};

    for (int t = 0; t < T_; t++) {
        const int phase = t & 1;
        const float* hT  = &g_hT[phase][dir][0][0];
        float*       hTn = &g_hT[phase ^ 1][dir][0][0];
        const float* xp  = g_xp + ((size_t)dir * T_ + t) * B_ * G4;

        float xg[2][4];
#pragma unroll
        for (int r = 0; r < 2; r++)
#pragma unroll
            for (int q = 0; q < 4; q++)
                xg[r][q] = __ldg(xp + (size_t)cell_b[r] * G4 + q * H_ + jt * 16 + cell_j[r]);

        u64 acc[4][4];
#pragma unroll
        for (int p = 0; p < 4; p++)
#pragma unroll
            for (int j = 0; j < 4; j++) acc[p][j] = 0ull;

#define ISSUE(s) do {                                                             \
            const int _s = (s);                                                   \
            const int _buf = _s % 3;                                              \
            const u32 _ad = sA_u + (u32)(_buf * BK * 64 * 4);                     \
            const u32 _bd = sB_u + (u32)(_buf * BK * 64 * 4);                     \
            cp_async16(_ad + (u32)tid * 16, hT + (size_t)_s * 2048 + tid * 4);    \
            cp_async16(_bd + b_sm_off,                                            \
                       wT + (size_t)(_s * BK + b_kk) * G4 + bcol_off);            \
            cp_commit();                                                          \
        } while (0)

        ISSUE(0);
        ISSUE(1);

        for (int s = 0; s < NSTAGE; s++) {
            if (s + 1 < NSTAGE) cp_wait1(); else cp_wait0();
            __syncthreads();
            if (s + 2 < NSTAGE) ISSUE(s + 2);

            const float* A  = sA + (s % 3) * (BK * 64) + g * 8 * 64 + tr * 8;
            const float* Bm = sB + (s % 3) * (BK * 64) + g * 8 * 64 + tc * 4;
#pragma unroll
            for (int kk = 0; kk < 8; kk++) {
                const float* ap = A + kk * 64;
                u64 a0 = *(const u64*)(ap + 0);
                u64 a1 = *(const u64*)(ap + 2);
                u64 a2 = *(const u64*)(ap + 4);
                u64 a3 = *(const u64*)(ap + 6);
                float4 b4 = *(const float4*)(Bm + kk * 64);
                u64 b0 = rep2(b4.x), b1 = rep2(b4.y), b2 = rep2(b4.z), b3 = rep2(b4.w);
                fma2(acc[0][0], a0, b0); fma2(acc[0][1], a0, b1); fma2(acc[0][2], a0, b2); fma2(acc[0][3], a0, b3);
                fma2(acc[1][0], a1, b0); fma2(acc[1][1], a1, b1); fma2(acc[1][2], a1, b2); fma2(acc[1][3], a1, b3);
                fma2(acc[2][0], a2, b0); fma2(acc[2][1], a2, b1); fma2(acc[2][2], a2, b2); fma2(acc[2][3], a2, b3);
                fma2(acc[3][0], a3, b0); fma2(acc[3][1], a3, b1); fma2(acc[3][2], a3, b2); fma2(acc[3][3], a3, b3);
            }
        }
#undef ISSUE

        // RACE FIX: all warps finish reading the last ring buffers before the
        // sG alias (regions 0-2 overlap the ring) is written.
        __syncthreads();

        // ---- write this group's partials into region g ----
        {
            float* dst = sG + g * SG_REGION;
#pragma unroll
            for (int i = 0; i < 8; i++) {
                int m = tr * 8 + i;
                int p = i >> 1;
                float v0 = (i & 1) ? hi32(acc[p][0]) : lo32(acc[p][0]);
                float v1 = (i & 1) ? hi32(acc[p][1]) : lo32(acc[p][1]);
                float v2 = (i & 1) ? hi32(acc[p][2]) : lo32(acc[p][2]);
                float v3 = (i & 1) ? hi32(acc[p][3]) : lo32(acc[p][3]);
                *(float4*)(dst + m * SG_STRIDE + tc * 4) = make_float4(v0, v1, v2, v3);
            }
        }
        __syncthreads();

        // ---- activation: sum 4 partials per gate + xp ----
#pragma unroll
        for (int r = 0; r < 2; r++) {
            int b = cell_b[r], j = cell_j[r];
            int jc = jt * 16 + j;
            const int base = b * SG_STRIDE;

            float ig = xg[r][0], fg = xg[r][1], gg = xg[r][2], og = xg[r][3];
#pragma unroll
            for (int q = 0; q < 4; q++) {
                const float* rgn = sG + q * SG_REGION + base;
                ig += rgn[     j];
                fg += rgn[16 + j];
                gg += rgn[32 + j];
                og += rgn[48 + j];
            }

            float si = 1.0f / (1.0f + __expf(-ig));
            float sf = 1.0f / (1.0f + __expf(-fg));
            float so = 1.0f / (1.0f + __expf(-og));
            float cn = sf * creg[r] + si * tanhf(gg);
            float hn = so * tanhf(cn);
            creg[r] = cn;

            hTn[jc * B_ + b] = hn;
            out[((size_t)b * T_ + t) * (2 * H_) + dir * H_ + jc] = hn;

            if (t == T_ - 1) {
                const size_t base2 = (size_t)B_ * T_ * 2 * H_;
                out[base2 + (dir ? 2 : 0) * (size_t)BH + b * H_ + jc] = hn;
                out[base2 + (dir ? 3 : 1) * (size_t)BH + b * H_ + jc] = cn;
            }
        }

        // ---- grid barrier ----
        __threadfence();
        __syncthreads();
        if (tid == 0) {
            unsigned ticket = atomicAdd(&g_bar_count, 1u);
            if (ticket == NCTA - 1) {
                g_bar_count = 0;
                __threadfence();
                g_bar_sense = (unsigned)(t + 1);
            } else {
                while (g_bar_sense < (unsigned)(t + 1)) { __nanosleep(32); }
            }
        }
        __syncthreads();
    }
}

// ---------------------------------------------------------------------------
// Launch
// ---------------------------------------------------------------------------
extern "C" void kernel_launch(void* const* d_in, const int* in_sizes, int n_in,
                              void* d_out, int out_size) {
    (void)in_sizes; (void)n_in; (void)out_size;
    const float* x       = (const float*)d_in[0];
    const float* w_ih_fw = (const float*)d_in[1];
    const float* w_hh_fw = (const float*)d_in[2];
    const float* b_ih_fw = (const float*)d_in[3];
    const float* b_hh_fw = (const float*)d_in[4];
    const float* w_ih_bw = (const float*)d_in[5];
    const float* w_hh_bw = (const float*)d_in[6];
    const float* b_ih_bw = (const float*)d_in[7];
    const float* b_hh_bw = (const float*)d_in[8];
    float* out = (float*)d_out;

    cudaFuncSetAttribute(lstm_persistent_kernel,
                         cudaFuncAttributeMaxDynamicSharedMemorySize, SMEM_BYTES);

    init_state_kernel<<<(2 * BH + 255) / 256, 256>>>();

    dim3 gtw(G4 / 32, H_ / 32, 2);
    transpose_w_kernel<<<gtw, 256>>>(w_hh_fw, w_hh_bw);

    dim3 gproj(64, T_, 2);
    input_proj_kernel<<<gproj, 128>>>(x, w_ih_fw, w_ih_bw,
                                      b_ih_fw, b_hh_fw, b_ih_bw, b_hh_bw);

    lstm_persistent_kernel<<<NCTA, NTHR, SMEM_BYTES>>>(out);
}